// round 1
// baseline (speedup 1.0000x reference)
#include <cuda_runtime.h>
#include <cuda_bf16.h>
#include <math.h>

#define NB 4096
#define NPER 2000
#define THREADS 256
#define NWARP (THREADS / 32)

// Per-event penalty scratch (no device allocation allowed).
__device__ float g_pen[NB];

__global__ void __launch_bounds__(THREADS) cov_pen_kernel(const float4* __restrict__ x) {
    const int b = blockIdx.x;
    const float4* base = x + (size_t)b * NPER;

    // 14 accumulators: sums x,y,z,w; second moments xx,xy,xz,xw,yy,yz,yw,zz,zw,ww
    float acc[14];
#pragma unroll
    for (int j = 0; j < 14; j++) acc[j] = 0.0f;

    for (int i = threadIdx.x; i < NPER; i += THREADS) {
        float4 v = __ldg(base + i);
        acc[0] += v.x; acc[1] += v.y; acc[2] += v.z; acc[3] += v.w;
        acc[4]  = fmaf(v.x, v.x, acc[4]);
        acc[5]  = fmaf(v.x, v.y, acc[5]);
        acc[6]  = fmaf(v.x, v.z, acc[6]);
        acc[7]  = fmaf(v.x, v.w, acc[7]);
        acc[8]  = fmaf(v.y, v.y, acc[8]);
        acc[9]  = fmaf(v.y, v.z, acc[9]);
        acc[10] = fmaf(v.y, v.w, acc[10]);
        acc[11] = fmaf(v.z, v.z, acc[11]);
        acc[12] = fmaf(v.z, v.w, acc[12]);
        acc[13] = fmaf(v.w, v.w, acc[13]);
    }

    __shared__ float red[NWARP][14];
    const int lane = threadIdx.x & 31;
    const int warp = threadIdx.x >> 5;
#pragma unroll
    for (int j = 0; j < 14; j++) {
        float v = acc[j];
#pragma unroll
        for (int off = 16; off; off >>= 1) v += __shfl_down_sync(0xffffffffu, v, off);
        if (lane == 0) red[warp][j] = v;
    }
    __syncthreads();

    if (threadIdx.x == 0) {
        float t[14];
#pragma unroll
        for (int j = 0; j < 14; j++) {
            float v = red[0][j];
#pragma unroll
            for (int w = 1; w < NWARP; w++) v += red[w][j];
            t[j] = v;
        }

        const float invN = 1.0f / (float)NPER;
        const float m0 = t[0] * invN, m1 = t[1] * invN, m2 = t[2] * invN, m3 = t[3] * invN;

        float A[4][4];
        A[0][0] = t[4]  * invN - m0 * m0;
        A[0][1] = A[1][0] = t[5]  * invN - m0 * m1;
        A[0][2] = A[2][0] = t[6]  * invN - m0 * m2;
        A[0][3] = A[3][0] = t[7]  * invN - m0 * m3;
        A[1][1] = t[8]  * invN - m1 * m1;
        A[1][2] = A[2][1] = t[9]  * invN - m1 * m2;
        A[1][3] = A[3][1] = t[10] * invN - m1 * m3;
        A[2][2] = t[11] * invN - m2 * m2;
        A[2][3] = A[3][2] = t[12] * invN - m2 * m3;
        A[3][3] = t[13] * invN - m3 * m3;

        // Shift by trace/4: eigensolve on a small-magnitude matrix for fp32 accuracy.
        const float mu = 0.25f * (A[0][0] + A[1][1] + A[2][2] + A[3][3]);
        A[0][0] -= mu; A[1][1] -= mu; A[2][2] -= mu; A[3][3] -= mu;

        // Cyclic Jacobi, 6 sweeps, fully unrolled (all indices constant -> registers).
#pragma unroll
        for (int sweep = 0; sweep < 6; sweep++) {
#pragma unroll
            for (int p = 0; p < 3; p++) {
#pragma unroll
                for (int q = p + 1; q < 4; q++) {
                    float apq = A[p][q];
                    if (fabsf(apq) > 1e-20f) {
                        float theta = (A[q][q] - A[p][p]) * 0.5f / apq;
                        float tt = copysignf(1.0f, theta) /
                                   (fabsf(theta) + sqrtf(fmaf(theta, theta, 1.0f)));
                        float c = rsqrtf(fmaf(tt, tt, 1.0f));
                        float s = tt * c;
                        float app = A[p][p], aqq = A[q][q];
                        A[p][p] = app - tt * apq;
                        A[q][q] = aqq + tt * apq;
                        A[p][q] = 0.0f; A[q][p] = 0.0f;
#pragma unroll
                        for (int k = 0; k < 4; k++) {
                            if (k == p || k == q) continue;
                            float akp = A[k][p], akq = A[k][q];
                            float np = c * akp - s * akq;
                            float nq = s * akp + c * akq;
                            A[k][p] = np; A[p][k] = np;
                            A[k][q] = nq; A[q][k] = nq;
                        }
                    }
                }
            }
        }

        float mn = fminf(fminf(A[0][0], A[1][1]), fminf(A[2][2], A[3][3]));
        float eigmin = mu + mn;              // min eigenvalue of cov
        float r = mu / (eigmin + 1e-6f) - 1.0f;  // mean(eig) == trace/4 == mu
        g_pen[b] = logf(fmaf(r, r, 1.0f));
    }
}

// Deterministic fixed-tree reduction of the 4096 penalties into the scalar output.
__global__ void __launch_bounds__(1024) sum_pen_kernel(float* __restrict__ out) {
    __shared__ double sred[32];
    const int tid = threadIdx.x;
    double v = 0.0;
#pragma unroll
    for (int i = 0; i < NB / 1024; i++) v += (double)g_pen[tid + i * 1024];
#pragma unroll
    for (int off = 16; off; off >>= 1) v += __shfl_down_sync(0xffffffffu, v, off);
    if ((tid & 31) == 0) sred[tid >> 5] = v;
    __syncthreads();
    if (tid < 32) {
        double w = sred[tid];
#pragma unroll
        for (int off = 16; off; off >>= 1) w += __shfl_down_sync(0xffffffffu, w, off);
        if (tid == 0) out[0] = (float)w;
    }
}

extern "C" void kernel_launch(void* const* d_in, const int* in_sizes, int n_in,
                              void* d_out, int out_size) {
    const float4* x = (const float4*)d_in[0];   // clust_space [B*NPER, 4], 16B rows
    // d_in[1] (batch_idx) is sorted with equal group sizes -> pure reshape, unused.
    cov_pen_kernel<<<NB, THREADS>>>(x);
    sum_pen_kernel<<<1, 1024>>>((float*)d_out);
}

// round 2
// speedup vs baseline: 1.7790x; 1.7790x over previous
#include <cuda_runtime.h>
#include <cuda_bf16.h>
#include <math.h>

#define NB   4096
#define NPER 2000
#define WPB  8                    // warps (events) per block
#define THREADS (WPB * 32)
#define NBLK (NB / WPB)           // 512 blocks

// Scratch (no device allocation allowed anywhere).
__device__ double g_part[NBLK];
__device__ unsigned int g_cnt = 0;

#define ACCUM(v)                                   \
    do {                                           \
        acc[0] += (v).x; acc[1] += (v).y;          \
        acc[2] += (v).z; acc[3] += (v).w;          \
        acc[4]  = fmaf((v).x, (v).x, acc[4]);      \
        acc[5]  = fmaf((v).x, (v).y, acc[5]);      \
        acc[6]  = fmaf((v).x, (v).z, acc[6]);      \
        acc[7]  = fmaf((v).x, (v).w, acc[7]);      \
        acc[8]  = fmaf((v).y, (v).y, acc[8]);      \
        acc[9]  = fmaf((v).y, (v).z, acc[9]);      \
        acc[10] = fmaf((v).y, (v).w, acc[10]);     \
        acc[11] = fmaf((v).z, (v).z, acc[11]);     \
        acc[12] = fmaf((v).z, (v).w, acc[12]);     \
        acc[13] = fmaf((v).w, (v).w, acc[13]);     \
    } while (0)

__global__ void __launch_bounds__(THREADS) llfill_fused_kernel(
        const float4* __restrict__ x, float* __restrict__ out) {
    const int lane = threadIdx.x & 31;
    const int warp = threadIdx.x >> 5;
    const int b = blockIdx.x * WPB + warp;          // event index, one warp per event
    const float4* base = x + (size_t)b * NPER;

    // 14 accumulators: sums x,y,z,w; second moments xx,xy,xz,xw,yy,yz,yw,zz,zw,ww
    float acc[14];
#pragma unroll
    for (int j = 0; j < 14; j++) acc[j] = 0.0f;

    // 2000 = 62*32 + 16. Main loop: 62 coalesced LDG.128 per warp, unroll 8 -> MLP ~8.
#pragma unroll 8
    for (int k = 0; k < 62; k++) {
        float4 v = __ldg(base + lane + 32 * k);
        ACCUM(v);
    }
    if (lane < 16) {
        float4 v = __ldg(base + 1984 + lane);
        ACCUM(v);
    }

    // Warp-level shuffle reduce of the 14 moments (no smem, no barrier).
#pragma unroll
    for (int j = 0; j < 14; j++) {
        float v = acc[j];
#pragma unroll
        for (int off = 16; off; off >>= 1) v += __shfl_down_sync(0xffffffffu, v, off);
        acc[j] = v;
    }

    __shared__ float spen[WPB];

    if (lane == 0) {
        const float invN = 1.0f / (float)NPER;
        const float m0 = acc[0] * invN, m1 = acc[1] * invN;
        const float m2 = acc[2] * invN, m3 = acc[3] * invN;

        float A[4][4];
        A[0][0] = acc[4]  * invN - m0 * m0;
        A[0][1] = A[1][0] = acc[5]  * invN - m0 * m1;
        A[0][2] = A[2][0] = acc[6]  * invN - m0 * m2;
        A[0][3] = A[3][0] = acc[7]  * invN - m0 * m3;
        A[1][1] = acc[8]  * invN - m1 * m1;
        A[1][2] = A[2][1] = acc[9]  * invN - m1 * m2;
        A[1][3] = A[3][1] = acc[10] * invN - m1 * m3;
        A[2][2] = acc[11] * invN - m2 * m2;
        A[2][3] = A[3][2] = acc[12] * invN - m2 * m3;
        A[3][3] = acc[13] * invN - m3 * m3;

        // Shift by trace/4 so fp32 Jacobi works on a small-magnitude matrix.
        const float mu = 0.25f * (A[0][0] + A[1][1] + A[2][2] + A[3][3]);
        A[0][0] -= mu; A[1][1] -= mu; A[2][2] -= mu; A[3][3] -= mu;

        // Cyclic Jacobi, 6 sweeps, fully unrolled (constant indices -> registers).
#pragma unroll
        for (int sweep = 0; sweep < 6; sweep++) {
#pragma unroll
            for (int p = 0; p < 3; p++) {
#pragma unroll
                for (int q = p + 1; q < 4; q++) {
                    float apq = A[p][q];
                    if (fabsf(apq) > 1e-20f) {
                        float theta = (A[q][q] - A[p][p]) * 0.5f / apq;
                        float tt = copysignf(1.0f, theta) /
                                   (fabsf(theta) + sqrtf(fmaf(theta, theta, 1.0f)));
                        float c = rsqrtf(fmaf(tt, tt, 1.0f));
                        float s = tt * c;
                        A[p][p] -= tt * apq;
                        A[q][q] += tt * apq;
                        A[p][q] = 0.0f; A[q][p] = 0.0f;
#pragma unroll
                        for (int k = 0; k < 4; k++) {
                            if (k == p || k == q) continue;
                            float akp = A[k][p], akq = A[k][q];
                            float np = c * akp - s * akq;
                            float nq = s * akp + c * akq;
                            A[k][p] = np; A[p][k] = np;
                            A[k][q] = nq; A[q][k] = nq;
                        }
                    }
                }
            }
        }

        float mn = fminf(fminf(A[0][0], A[1][1]), fminf(A[2][2], A[3][3]));
        float eigmin = mu + mn;                         // min eigenvalue of cov
        float r = mu / (eigmin + 1e-6f) - 1.0f;         // mean(eig) == trace/4 == mu
        spen[warp] = logf(fmaf(r, r, 1.0f));
    }
    __syncthreads();

    // Per-block partial (fixed order -> deterministic), then last-block final reduce.
    __shared__ bool is_last;
    if (threadIdx.x == 0) {
        double s = 0.0;
#pragma unroll
        for (int w = 0; w < WPB; w++) s += (double)spen[w];
        g_part[blockIdx.x] = s;
        __threadfence();
        unsigned int t = atomicInc(&g_cnt, NBLK - 1);   // wraps to 0 -> reusable per launch
        is_last = (t == NBLK - 1);
    }
    __syncthreads();

    if (is_last) {
        // 256 threads reduce 512 doubles with a fixed tree (deterministic).
        volatile double* vp = g_part;
        const int tid = threadIdx.x;
        double v = vp[tid] + vp[tid + THREADS];
#pragma unroll
        for (int off = 16; off; off >>= 1) v += __shfl_down_sync(0xffffffffu, v, off);
        __shared__ double sred[WPB];
        if ((tid & 31) == 0) sred[tid >> 5] = v;
        __syncthreads();
        if (tid == 0) {
            double tot = 0.0;
#pragma unroll
            for (int w = 0; w < WPB; w++) tot += sred[w];
            out[0] = (float)tot;
        }
    }
}

extern "C" void kernel_launch(void* const* d_in, const int* in_sizes, int n_in,
                              void* d_out, int out_size) {
    const float4* x = (const float4*)d_in[0];   // clust_space [B*NPER, 4], 16B rows
    // d_in[1] (batch_idx) is sorted with equal group sizes -> pure reshape, unused.
    llfill_fused_kernel<<<NBLK, THREADS>>>(x, (float*)d_out);
}